// round 8
// baseline (speedup 1.0000x reference)
#include <cuda_runtime.h>

#define KS2      4
#define BASIS    8
#define HIDDEN   16
#define TS       512
#define LOGIT_LO (-16.0f)
#define LOGIT_HI (16.0f)

// Piecewise-linear table of out = f(logit). Entry j = {f_j, f_{j+1} - f_j}.
// 512 * 8B = 4 KB -> 32 L1 lines; a warp's 32 lookups hit ~10 hot lines.
__device__ float2 g_table[TS];

__device__ __forceinline__ float eval_f(float logit,
                                        const float* __restrict__ basis,
                                        const float* __restrict__ w1,
                                        const float* __restrict__ b1,
                                        const float* __restrict__ w2,
                                        const float* __restrict__ b2)
{
    // act = sigmoid(logit - THRESHOLD), THRESHOLD = 0
    float a = 1.0f / (1.0f + expf(-logit));

    float feats[BASIS];
#pragma unroll
    for (int b = 0; b < BASIS; ++b) {
        float s = 0.0f;
#pragma unroll
        for (int j = 0; j < KS2; ++j) {
            float d = a - basis[b * KS2 + j];
            s = fmaf(d, d, s);
        }
        feats[b] = expf(-s);   // GAMMA = 1
    }

    float out = b2[0];
#pragma unroll
    for (int i = 0; i < HIDDEN; ++i) {
        float h = b1[i];
#pragma unroll
        for (int b = 0; b < BASIS; ++b)
            h = fmaf(feats[b], w1[b * HIDDEN + i], h);
        out = fmaf(tanhf(h), w2[i], out);
    }
    return out;
}

__global__ void build_table_kernel(const float* __restrict__ basis,
                                   const float* __restrict__ w1,
                                   const float* __restrict__ b1,
                                   const float* __restrict__ w2,
                                   const float* __restrict__ b2)
{
    int j = blockIdx.x * blockDim.x + threadIdx.x;
    if (j >= TS) return;
    const float step = (LOGIT_HI - LOGIT_LO) / (float)(TS - 1);
    float x0 = LOGIT_LO + (float)j * step;
    float f0 = eval_f(x0, basis, w1, b1, w2, b2);
    float f1 = (j < TS - 1) ? eval_f(x0 + step, basis, w1, b1, w2, b2) : f0;
    g_table[j] = make_float2(f0, f1 - f0);
}

__device__ __forceinline__ float table_lookup(float logit)
{
    const float scale = (float)(TS - 1) / (LOGIT_HI - LOGIT_LO);
    float u = (logit - LOGIT_LO) * scale;
    u = fminf(fmaxf(u, 0.0f), (float)(TS - 2) + 0.999f);
    int j = (int)u;
    if (j > TS - 2) j = TS - 2;
    float frac = u - (float)j;
    float2 tv = __ldg(&g_table[j]);
    return fmaf(frac, tv.y, tv.x);
}

// 8 patches per thread: 8 front-batched LDG.128 (high MLP), 8 L1-resident
// table lookups, 2 STG.128.
__global__ void __launch_bounds__(256)
patch_kernel(const float* __restrict__ data,
             const float* __restrict__ conv_w,
             const float* __restrict__ conv_b,
             float* __restrict__ out,
             int N)
{
    float cw0 = __ldg(conv_w + 0);
    float cw1 = __ldg(conv_w + 1);
    float cw2 = __ldg(conv_w + 2);
    float cw3 = __ldg(conv_w + 3);
    float cb  = __ldg(conv_b);

    long long t  = (long long)blockIdx.x * blockDim.x + threadIdx.x;
    long long i0 = t * 8;   // first patch index for this thread

    if (i0 + 8 <= (long long)N) {
        const float4* dp = (const float4*)data + i0;
        float4 v[8];
#pragma unroll
        for (int k = 0; k < 8; ++k)
            v[k] = __ldg(dp + k);

        float r[8];
#pragma unroll
        for (int k = 0; k < 8; ++k) {
            float logit = fmaf(v[k].x, cw0,
                          fmaf(v[k].y, cw1,
                          fmaf(v[k].z, cw2,
                          fmaf(v[k].w, cw3, cb))));
            r[k] = table_lookup(logit);
        }

        float4* op = (float4*)out + t * 2;
        op[0] = make_float4(r[0], r[1], r[2], r[3]);
        op[1] = make_float4(r[4], r[5], r[6], r[7]);
    } else if (i0 < (long long)N) {
        for (long long i = i0; i < (long long)N; ++i) {
            float a0 = data[i * 4 + 0];
            float a1 = data[i * 4 + 1];
            float a2 = data[i * 4 + 2];
            float a3 = data[i * 4 + 3];
            float logit = fmaf(a0, cw0, fmaf(a1, cw1, fmaf(a2, cw2, fmaf(a3, cw3, cb))));
            out[i] = table_lookup(logit);
        }
    }
}

extern "C" void kernel_launch(void* const* d_in, const int* in_sizes, int n_in,
                              void* d_out, int out_size)
{
    const float* data   = (const float*)d_in[0];
    const float* conv_w = (const float*)d_in[1];
    const float* conv_b = (const float*)d_in[2];
    const float* basis  = (const float*)d_in[3];
    const float* w1     = (const float*)d_in[4];
    const float* b1     = (const float*)d_in[5];
    const float* w2     = (const float*)d_in[6];
    const float* b2     = (const float*)d_in[7];

    int N = in_sizes[0] / KS2;   // in_sizes[0] = N * KS * KS

    // 1) Build f(logit) table from this run's weights (deterministic, tiny).
    build_table_kernel<<<(TS + 255) / 256, 256>>>(basis, w1, b1, w2, b2);

    // 2) Streaming per-patch kernel, 8 patches per thread, full grid.
    long long nthreads = ((long long)N + 7) / 8;
    int threads = 256;
    long long blocks = (nthreads + threads - 1) / threads;
    if (blocks < 1) blocks = 1;
    patch_kernel<<<(unsigned int)blocks, threads>>>(data, conv_w, conv_b,
                                                    (float*)d_out, N);
}

// round 9
// speedup vs baseline: 1.3665x; 1.3665x over previous
#include <cuda_runtime.h>

#define KS2      4
#define BASIS    8
#define HIDDEN   16
#define TS       512
#define LOGIT_LO (-16.0f)
#define LOGIT_HI (16.0f)

// Piecewise-linear table of out = f(logit). Entry j = {f_j, f_{j+1} - f_j}.
// TS=512 validated at rel_err 4.2e-5 (threshold 1e-3). 4 KB -> lives in smem.
__device__ float2 g_table[TS];

__device__ __forceinline__ float eval_f(float logit,
                                        const float* __restrict__ basis,
                                        const float* __restrict__ w1,
                                        const float* __restrict__ b1,
                                        const float* __restrict__ w2,
                                        const float* __restrict__ b2)
{
    // act = sigmoid(logit - THRESHOLD), THRESHOLD = 0
    float a = 1.0f / (1.0f + expf(-logit));

    float feats[BASIS];
#pragma unroll
    for (int b = 0; b < BASIS; ++b) {
        float s = 0.0f;
#pragma unroll
        for (int j = 0; j < KS2; ++j) {
            float d = a - basis[b * KS2 + j];
            s = fmaf(d, d, s);
        }
        feats[b] = expf(-s);   // GAMMA = 1
    }

    float out = b2[0];
#pragma unroll
    for (int i = 0; i < HIDDEN; ++i) {
        float h = b1[i];
#pragma unroll
        for (int b = 0; b < BASIS; ++b)
            h = fmaf(feats[b], w1[b * HIDDEN + i], h);
        out = fmaf(tanhf(h), w2[i], out);
    }
    return out;
}

__global__ void build_table_kernel(const float* __restrict__ basis,
                                   const float* __restrict__ w1,
                                   const float* __restrict__ b1,
                                   const float* __restrict__ w2,
                                   const float* __restrict__ b2)
{
    int j = blockIdx.x * blockDim.x + threadIdx.x;
    if (j >= TS) return;
    const float step = (LOGIT_HI - LOGIT_LO) / (float)(TS - 1);
    float x0 = LOGIT_LO + (float)j * step;
    float f0 = eval_f(x0, basis, w1, b1, w2, b2);
    float f1 = (j < TS - 1) ? eval_f(x0 + step, basis, w1, b1, w2, b2) : f0;
    g_table[j] = make_float2(f0, f1 - f0);
}

__device__ __forceinline__ float table_lookup_smem(const float2* __restrict__ tab,
                                                   float logit)
{
    const float scale = (float)(TS - 1) / (LOGIT_HI - LOGIT_LO);
    float u = (logit - LOGIT_LO) * scale;
    u = fminf(fmaxf(u, 0.0f), (float)(TS - 2) + 0.999f);
    int j = (int)u;
    if (j > TS - 2) j = TS - 2;
    float frac = u - (float)j;
    float2 tv = tab[j];                 // LDS.64, random over 4 KB
    return fmaf(frac, tv.y, tv.x);
}

// R1-winning shape (4 patches/thread, full grid) + 4 KB smem lookup table.
__global__ void __launch_bounds__(256)
patch_kernel(const float* __restrict__ data,
             const float* __restrict__ conv_w,
             const float* __restrict__ conv_b,
             float* __restrict__ out,
             long long N)
{
    __shared__ float2 tab[TS];

    // Copy 4 KB table from L2-resident global into shared (one float4 / thread).
    {
        const float4* gt = (const float4*)g_table;   // TS/2 = 256 float4s
        if (threadIdx.x < TS / 2) {
            float4 v = __ldg(gt + threadIdx.x);
            tab[2 * threadIdx.x + 0] = make_float2(v.x, v.y);
            tab[2 * threadIdx.x + 1] = make_float2(v.z, v.w);
        }
    }

    float cw0 = __ldg(conv_w + 0);
    float cw1 = __ldg(conv_w + 1);
    float cw2 = __ldg(conv_w + 2);
    float cw3 = __ldg(conv_w + 3);
    float cb  = __ldg(conv_b);

    __syncthreads();

    long long t  = (long long)blockIdx.x * blockDim.x + threadIdx.x;
    long long i0 = t * 4;

    if (i0 + 4 <= N) {
        const float4* dp = (const float4*)data + i0;
        float4 v[4];
#pragma unroll
        for (int k = 0; k < 4; ++k)
            v[k] = __ldg(dp + k);

        float r[4];
#pragma unroll
        for (int k = 0; k < 4; ++k) {
            float logit = fmaf(v[k].x, cw0,
                          fmaf(v[k].y, cw1,
                          fmaf(v[k].z, cw2,
                          fmaf(v[k].w, cw3, cb))));
            r[k] = table_lookup_smem(tab, logit);
        }
        ((float4*)out)[t] = make_float4(r[0], r[1], r[2], r[3]);
    } else if (i0 < N) {
        for (long long i = i0; i < N; ++i) {
            float a0 = data[i * 4 + 0];
            float a1 = data[i * 4 + 1];
            float a2 = data[i * 4 + 2];
            float a3 = data[i * 4 + 3];
            float logit = fmaf(a0, cw0, fmaf(a1, cw1, fmaf(a2, cw2, fmaf(a3, cw3, cb))));
            out[i] = table_lookup_smem(tab, logit);
        }
    }
}

extern "C" void kernel_launch(void* const* d_in, const int* in_sizes, int n_in,
                              void* d_out, int out_size)
{
    const float* data   = (const float*)d_in[0];
    const float* conv_w = (const float*)d_in[1];
    const float* conv_b = (const float*)d_in[2];
    const float* basis  = (const float*)d_in[3];
    const float* w1     = (const float*)d_in[4];
    const float* b1     = (const float*)d_in[5];
    const float* w2     = (const float*)d_in[6];
    const float* b2     = (const float*)d_in[7];

    long long N = (long long)in_sizes[0] / KS2;   // in_sizes[0] = N * KS * KS

    // 1) Build f(logit) table from this run's weights (deterministic, tiny).
    build_table_kernel<<<(TS + 255) / 256, 256>>>(basis, w1, b1, w2, b2);

    // 2) Streaming per-patch kernel, 4 patches per thread, full grid.
    long long nthreads = (N + 3) / 4;
    int threads = 256;
    long long blocks = (nthreads + threads - 1) / threads;
    if (blocks < 1) blocks = 1;
    patch_kernel<<<(unsigned int)blocks, threads>>>(data, conv_w, conv_b,
                                                    (float*)d_out, N);
}